// round 5
// baseline (speedup 1.0000x reference)
#include <cuda_runtime.h>
#include <math.h>
#include <stdint.h>

// Problem constants
#define Bq   2
#define Pq   4000
#define NPq  4096
#define Dq   64
#define Mq   512
#define HWq  214272            // 496 * 432

// Output section offsets (in floats)
static constexpr long O1 = (long)Bq * 128 * HWq;          // spatial_features_point
static constexpr long O2 = 2 * O1;                        // spatial_scale_features
static constexpr long O3 = O2 + (long)Bq * 64 * HWq;      // point_positive_features
static constexpr long O4 = O3 + (long)Bq * Pq * 64;       // memory_positive_features

// Winner map for duplicate-index resolution (last-write-wins => max pillar idx)
__device__ int g_winner[Bq * HWq];

// ---------------------------------------------------------------------------
// Zero-fill the spatial region of the output (first O3 floats), float4 stores.
// ---------------------------------------------------------------------------
__global__ void zero_kernel(float4* __restrict__ out, long n4) {
    long i = (long)blockIdx.x * blockDim.x + threadIdx.x;
    long stride = (long)gridDim.x * blockDim.x;
    float4 z = make_float4(0.f, 0.f, 0.f, 0.f);
    for (; i < n4; i += stride) out[i] = z;
}

__global__ void winner_reset_kernel() {
    int i = blockIdx.x * blockDim.x + threadIdx.x;
    if (i < Bq * HWq) g_winner[i] = -1;
}

__global__ void winner_mark_kernel(const int* __restrict__ idxs) {
    int i = blockIdx.x * blockDim.x + threadIdx.x;
    if (i < Bq * Pq) {
        int b = i / Pq;
        int p = i - b * Pq;
        atomicMax(&g_winner[b * HWq + idxs[i]], p);
    }
}

// ---------------------------------------------------------------------------
// Fully-unrolled top-8 insertion (keeps arrays in registers; sorted descending)
// ---------------------------------------------------------------------------
__device__ __forceinline__ void top8_insert(float (&tv)[8], int (&ti)[8], float v, int n) {
    if (v > tv[7]) {
#pragma unroll
        for (int s = 0; s < 8; ++s) {
            if (v > tv[s]) {
                float a = tv[s]; int b = ti[s];
                tv[s] = v; ti[s] = n;
                v = a; n = b;
            }
        }
    }
}

// ---------------------------------------------------------------------------
// Fused GEMM + top-8 + softmax + weighted gather.
//   For each pillar p: logits[n] = pillars[p] . X[n]  (n in [0,N))
//   top-8 logits -> softmax -> out[p] = sum_k w_k * X[top_k]
// Block: 256 threads, 64 pillars/block, 64-point tiles, 4x4 micro-tile/thread.
// Dynamic smem: 66048 bytes (tiles, then reused as merge candidate buffers).
// ---------------------------------------------------------------------------
__global__ __launch_bounds__(256) void topk_agg_kernel(
    const float* __restrict__ pillars,  // [B, P, 64]
    const float* __restrict__ X,        // [B, N, 64] or [N, 64] (xStride = 0)
    float* __restrict__ outp,           // [B, P, 64]
    int N, int xStride)
{
    extern __shared__ float smem[];
    float* sP = smem;                 // [64][68] pillar tile, k-major
    float* sX = smem + 64 * 68;       // [64][68] point tile,  k-major
    float* candV = smem;              // [64][129] (reused after main loop)
    int*   candI = (int*)(smem + 64 * 129);

    const int b = blockIdx.y;
    const int pBase = blockIdx.x * 64;
    const float* pil = pillars + (size_t)b * Pq * 64;
    const float* Xb  = X + (size_t)b * xStride;
    float* outb = outp + (size_t)b * Pq * 64;

    const int tid = threadIdx.x;
    const int ni = tid & 15;   // point sub-tile  (4 points)
    const int mi = tid >> 4;   // pillar sub-tile (4 pillars)

    // Load pillar tile transposed: sP[k][m] = pillars[pBase+m][k]
#pragma unroll
    for (int i = 0; i < 16; i++) {
        int lin = tid + 256 * i;
        int m = lin >> 6, k = lin & 63;
        int gp = pBase + m; if (gp >= Pq) gp = Pq - 1;
        sP[k * 68 + m] = pil[(size_t)gp * 64 + k];
    }

    float topv[4][8]; int topi[4][8];
#pragma unroll
    for (int a = 0; a < 4; a++)
#pragma unroll
        for (int s = 0; s < 8; s++) { topv[a][s] = -INFINITY; topi[a][s] = 0; }

    for (int nB = 0; nB < N; nB += 64) {
        __syncthreads();
        // Load X tile transposed: sX[k][n] = X[nB+n][k]
#pragma unroll
        for (int i = 0; i < 16; i++) {
            int lin = tid + 256 * i;
            int n = lin >> 6, k = lin & 63;
            sX[k * 68 + n] = Xb[(size_t)(nB + n) * 64 + k];
        }
        __syncthreads();

        float acc[4][4];
#pragma unroll
        for (int a = 0; a < 4; a++) { acc[a][0] = acc[a][1] = acc[a][2] = acc[a][3] = 0.f; }

#pragma unroll 8
        for (int k = 0; k < 64; k++) {
            float4 pf = *(const float4*)&sP[k * 68 + mi * 4];
            float4 xf = *(const float4*)&sX[k * 68 + ni * 4];
            float pv[4] = {pf.x, pf.y, pf.z, pf.w};
            float xv[4] = {xf.x, xf.y, xf.z, xf.w};
#pragma unroll
            for (int a = 0; a < 4; a++)
#pragma unroll
                for (int c = 0; c < 4; c++)
                    acc[a][c] = fmaf(pv[a], xv[c], acc[a][c]);
        }

#pragma unroll
        for (int a = 0; a < 4; a++)
#pragma unroll
            for (int c = 0; c < 4; c++) {
                int n = nB + ni * 4 + c;
                top8_insert(topv[a], topi[a], acc[a][c], n);
            }
    }

    __syncthreads();
    // Dump per-thread top-8 lists into smem (128 candidates per pillar)
#pragma unroll
    for (int a = 0; a < 4; a++) {
        int m = 4 * mi + a;
#pragma unroll
        for (int s = 0; s < 8; s++) {
            candV[m * 129 + ni * 8 + s] = topv[a][s];
            candI[m * 129 + ni * 8 + s] = topi[a][s];
        }
    }
    __syncthreads();

    // One merge-thread per pillar: 128 candidates -> final top-8 -> softmax weights
    if (tid < 64) {
        int m = tid;
        float fv[8]; int fi[8];
#pragma unroll
        for (int s = 0; s < 8; s++) { fv[s] = -INFINITY; fi[s] = 0; }
        for (int j = 0; j < 128; j++) {
            float v = candV[m * 129 + j];
            int   n = candI[m * 129 + j];
            top8_insert(fv, fi, v, n);
        }
        float w[8]; float sum = 0.f;
#pragma unroll
        for (int s = 0; s < 8; s++) { w[s] = expf(fv[s] - fv[0]); sum += w[s]; }
        float inv = 1.f / sum;
#pragma unroll
        for (int s = 0; s < 8; s++) { candV[m * 129 + s] = w[s] * inv; candI[m * 129 + s] = fi[s]; }
    }
    __syncthreads();

    // Weighted gather: out[p][d] = sum_k w_k * X[idx_k][d]
#pragma unroll
    for (int i = 0; i < 16; i++) {
        int lin = tid + 256 * i;
        int m = lin >> 6, d = lin & 63;
        int gp = pBase + m;
        if (gp < Pq) {
            float s = 0.f;
#pragma unroll
            for (int kk = 0; kk < 8; kk++) {
                float w = candV[m * 129 + kk];
                int   n = candI[m * 129 + kk];
                s += w * Xb[(size_t)n * 64 + d];
            }
            outb[(size_t)gp * 64 + d] = s;
        }
    }
}

// ---------------------------------------------------------------------------
// Scatter: winner pillar per BEV column writes the three dense grids.
// ---------------------------------------------------------------------------
__global__ __launch_bounds__(64) void scatter_kernel(
    const float* __restrict__ pillars, const float* __restrict__ scales,
    const float* __restrict__ posP,    const float* __restrict__ posM,
    const int* __restrict__ idxs,      float* __restrict__ out)
{
    int bp = blockIdx.x;
    int b = bp / Pq, p = bp - b * Pq;
    int col = idxs[bp];
    if (g_winner[b * HWq + col] != p) return;
    int d = threadIdx.x;

    size_t o = (size_t)bp * 64 + d;
    float pilv = pillars[o];
    float scv  = scales[o];
    float ppv  = posP[o];
    float pmv  = posM[o];

    float* sp  = out;             // spatial_features      [B,128,HW]: [pillars ; pos_mem]
    float* spp = out + (size_t)O1;// spatial_features_point [B,128,HW]: [pillars ; pos_point]
    float* sps = out + (size_t)O2;// spatial_scale_features [B, 64,HW]

    size_t base = (size_t)b * 128 * HWq + (size_t)d * HWq + col;
    sp [base] = pilv;
    sp [base + (size_t)64 * HWq] = pmv;
    spp[base] = pilv;
    spp[base + (size_t)64 * HWq] = ppv;
    sps[(size_t)b * 64 * HWq + (size_t)d * HWq + col] = scv;
}

// ---------------------------------------------------------------------------
extern "C" void kernel_launch(void* const* d_in, const int* in_sizes, int n_in,
                              void* d_out, int out_size) {
    (void)in_sizes; (void)n_in; (void)out_size;
    const float* pillars = (const float*)d_in[0];   // [B,P,64]
    const float* scales  = (const float*)d_in[1];   // [B,P,64]
    const float* points  = (const float*)d_in[2];   // [B,NP,64]
    const float* W       = (const float*)d_in[3];   // [M,64]
    const int*   idxs    = (const int*)d_in[4];     // [B,P]
    float* out = (float*)d_out;

    const int smemBytes = 66048;  // 2 * 64 * 129 * 4
    cudaFuncSetAttribute(topk_agg_kernel,
                         cudaFuncAttributeMaxDynamicSharedMemorySize, smemBytes);

    // 1) zero the spatial region (positive-feature sections are fully written)
    long n4 = O3 / 4;
    zero_kernel<<<4096, 256>>>((float4*)out, n4);

    // 2) duplicate-index winner resolution (last-write-wins => max p)
    winner_reset_kernel<<<(Bq * HWq + 255) / 256, 256>>>();
    winner_mark_kernel<<<(Bq * Pq + 255) / 256, 256>>>(idxs);

    // 3) fused attention stages
    dim3 grid((Pq + 63) / 64, Bq);
    topk_agg_kernel<<<grid, 256, smemBytes>>>(pillars, points, out + O3, NPq, NPq * 64);
    topk_agg_kernel<<<grid, 256, smemBytes>>>(pillars, W,      out + O4, Mq,  0);

    // 4) scatter winners into the dense BEV grids
    scatter_kernel<<<Bq * Pq, 64>>>(pillars, scales, out + O3, out + O4, idxs, out);
}